// round 10
// baseline (speedup 1.0000x reference)
#include <cuda_runtime.h>
#include <cuda_fp16.h>
#include <stdint.h>

#define D 128
#define NMAX 100000
#define EMAX 1000000
#define WPITCH 136                   // fp16 elems per smem row (128 + 8 pad)
#define PITCHB 272                   // bytes

#define TOT_CTAS 296
#define NODE_CTAS 192                // 96 per table half
#define HALF_CTAS 96
#define EDGE_CTAS 104                // TOT - NODE
#define NBK 64                       // edge buckets by max(row,col)
#define CH 1024                      // edge chunk size

// ---------------------------------------------------------------------------
// Device scratch (static — no cudaMalloc allowed)
// ---------------------------------------------------------------------------
__device__ __align__(16) __half g_A16[(size_t)(NMAX + 128) * 128];
__device__ __align__(16) __half g_B16[(size_t)(NMAX + 128) * 128];
__device__ __align__(16) uint4  g_eord[EMAX];     // {row, col, e, 0} bucketed

struct Sync {
    unsigned hist[NBK];
    unsigned boff[NBK + 1];
    unsigned bcur[NBK];
    unsigned ccur[NBK];
    unsigned ebar1, pfx, ebar2;
    unsigned tflag[2][64];           // done-tile bitmaps per half
};
__device__ Sync g_s;

// ---------------------------------------------------------------------------
// PTX helpers (sm_80-era only; safe on .target sm_103)
// ---------------------------------------------------------------------------
__device__ __forceinline__ uint32_t smem_u32(const void* p) {
    uint32_t a;
    asm("{ .reg .u64 t; cvta.to.shared.u64 t, %1; cvt.u32.u64 %0, t; }"
        : "=r"(a) : "l"(p));
    return a;
}

#define LDSM_X4(r0, r1, r2, r3, addr)                                           \
    asm volatile("ldmatrix.sync.aligned.m8n8.x4.shared.b16 {%0,%1,%2,%3},[%4];" \
                 : "=r"(r0), "=r"(r1), "=r"(r2), "=r"(r3) : "r"(addr))

#define LDSM_X2(r0, r1, addr)                                                \
    asm volatile("ldmatrix.sync.aligned.m8n8.x2.shared.b16 {%0,%1},[%2];"    \
                 : "=r"(r0), "=r"(r1) : "r"(addr))

#define MMA_F16(d, a0, a1, a2, a3, b0, b1)                                   \
    asm volatile("mma.sync.aligned.m16n8k16.row.col.f32.f16.f16.f32 "        \
                 "{%0,%1,%2,%3},{%4,%5,%6,%7},{%8,%9},{%0,%1,%2,%3};"        \
                 : "+f"((d)[0]), "+f"((d)[1]), "+f"((d)[2]), "+f"((d)[3])    \
                 : "r"(a0), "r"(a1), "r"(a2), "r"(a3), "r"(b0), "r"(b1))

// warp-aggregated atomicAdd of 1 per lane, keyed by bucket b
__device__ __forceinline__ unsigned agg_add(unsigned* arr, unsigned b) {
    unsigned am = __activemask();
    unsigned mask = __match_any_sync(am, b);
    int lane = threadIdx.x & 31;
    int leader = __ffs(mask) - 1;
    unsigned base = 0;
    if (lane == leader) base = atomicAdd(arr + b, __popc(mask));
    base = __shfl_sync(mask, base, leader);
    return base + __popc(mask & ((1u << lane) - 1));
}

__device__ __forceinline__ float edge_dot(uint4 a4, uint4 b4,
                                          float4 w2a, float4 w2b) {
    const half2 z2 = __floats2half2_rn(0.f, 0.f);
    half2 h0 = __hmax2(__hadd2(*(half2*)&a4.x, *(half2*)&b4.x), z2);
    half2 h1 = __hmax2(__hadd2(*(half2*)&a4.y, *(half2*)&b4.y), z2);
    half2 h2 = __hmax2(__hadd2(*(half2*)&a4.z, *(half2*)&b4.z), z2);
    half2 h3 = __hmax2(__hadd2(*(half2*)&a4.w, *(half2*)&b4.w), z2);
    float2 f0 = __half22float2(h0);
    float2 f1 = __half22float2(h1);
    float2 f2 = __half22float2(h2);
    float2 f3 = __half22float2(h3);
    return f0.x * w2a.x + f0.y * w2a.y + f1.x * w2a.z + f1.y * w2a.w
         + f2.x * w2b.x + f2.y * w2b.y + f3.x * w2b.z + f3.y * w2b.w;
}

// ---------------------------------------------------------------------------
// init: zero the sync block every launch (graph replays)
// ---------------------------------------------------------------------------
__global__ void init_kernel() {
    unsigned* p = (unsigned*)&g_s;
    int n = sizeof(Sync) / 4;
    for (int i = threadIdx.x; i < n; i += blockDim.x) p[i] = 0;
}

// ---------------------------------------------------------------------------
// fused kernel: node producers + bucket-gated edge consumers, one wave
// ---------------------------------------------------------------------------
__global__ void __launch_bounds__(256, 2)
fused_kernel(const float* __restrict__ z, const float* __restrict__ W1,
             const float* __restrict__ b1, const void* __restrict__ ei_raw,
             const float* __restrict__ W2, const float* __restrict__ b2,
             float* __restrict__ out, int N, int E)
{
    extern __shared__ char smem[];
    const uint32_t OF_C0  = 0;
    const uint32_t OF_C1  = 17408;
    const uint32_t OF_EPI = 34816;

    const uint32_t sb = smem_u32(smem);
    const int tid = threadIdx.x;
    const int w = tid >> 5;
    const int lane = tid & 31;
    const int bid = blockIdx.x;
    const int ntiles = (N + 63) / 64;

    const long long* ei64 = (const long long*)ei_raw;
    const int*       ei32 = (const int*)ei_raw;
    int is64 = 1;
#pragma unroll
    for (int i = 0; i < 8; i++) {
        long long v = __ldg(&ei64[i]);
        if (v < 0 || v >= (long long)N) is64 = 0;
    }

    if (bid < NODE_CTAS) {
        // =================== NODE ROLE ===================
        const int hb = (bid >= HALF_CTAS) ? 1 : 0;
        const int c  = hb ? bid - HALF_CTAS : bid;

        float4 rawreg[8];
        auto issue_ldg = [&](int t) {
            const int rows_valid = N - t * 64;
            const float4* src = (const float4*)(z + (size_t)t * 64 * 128);
#pragma unroll
            for (int q = 0; q < 8; q++) {
                int idx = tid + q * 256;
                int m = idx >> 5, j = idx & 31;
                rawreg[q] = (m < rows_valid) ? src[m * 32 + j]
                                             : make_float4(0.f, 0.f, 0.f, 0.f);
            }
        };
        auto cvt_sts = [&](uint32_t convoff) {
#pragma unroll
            for (int q = 0; q < 8; q++) {
                int idx = tid + q * 256;
                int m = idx >> 5, j = idx & 31;
                half2 h0 = __floats2half2_rn(rawreg[q].x, rawreg[q].y);
                half2 h1 = __floats2half2_rn(rawreg[q].z, rawreg[q].w);
                *(uint2*)(smem + convoff + (uint32_t)(m * 272 + j * 8)) =
                    make_uint2(*(uint32_t*)&h0, *(uint32_t*)&h1);
            }
        };

        if (c < ntiles) issue_ldg(c);

        // W1 -> fp16 fragments in registers (16 cols per warp)
        uint32_t whf[16][2];
        {
            const int n0 = w * 16;
            const uint32_t stg = (uint32_t)(OF_C0 + w * 2176);
            const uint32_t boffp = sb + stg
                + (uint32_t)((lane & 7) * 272 + ((lane >> 3) & 1) * 16);
#pragma unroll
            for (int half8 = 0; half8 < 2; half8++) {
#pragma unroll
                for (int q = 0; q < 32; q++) {
                    int idx = lane + q * 32;
                    int r = idx & 7, k = idx >> 3;
                    float x = W1[(size_t)(hb * 128 + k) * 128 + n0 + half8 * 8 + r];
                    *(__half*)(smem + stg + r * 272 + k * 2) = __float2half_rn(x);
                }
                __syncwarp();
#pragma unroll
                for (int ks = 0; ks < 8; ks++)
                    LDSM_X2(whf[ks * 2 + half8][0], whf[ks * 2 + half8][1],
                            boffp + (uint32_t)(ks * 32));
                __syncwarp();
            }
        }
        __syncthreads();

        if (c < ntiles) cvt_sts(OF_C0);

        float2 bb0 = make_float2(0.f, 0.f), bb1 = bb0;
        if (hb) {
            int cc = w * 16 + (lane & 3) * 2;
            bb0 = *(const float2*)(b1 + cc);
            bb1 = *(const float2*)(b1 + cc + 8);
        }
        __half* dsttab = hb ? g_B16 : g_A16;
        const uint32_t a_off = (uint32_t)((lane & 15) * WPITCH + (lane >> 4) * 8) * 2;
        const uint32_t Ah = sb + OF_C0 + a_off;

        int it = 0;
        for (int t = c; t < ntiles; t += HALF_CTAS) {
            const int tn = t + HALF_CTAS;
            __syncthreads();
            if (tn < ntiles) issue_ldg(tn);

            float acc[4][2][4];
#pragma unroll
            for (int mt = 0; mt < 4; mt++)
#pragma unroll
                for (int nt = 0; nt < 2; nt++)
#pragma unroll
                    for (int q = 0; q < 4; q++) acc[mt][nt][q] = 0.f;

            const uint32_t Abase = Ah + (uint32_t)(it * 17408);
#pragma unroll
            for (int ks = 0; ks < 8; ks++) {
                const uint32_t ko = (uint32_t)ks * 32;
#pragma unroll
                for (int mt = 0; mt < 4; mt++) {
                    uint32_t a0, a1, a2, a3;
                    LDSM_X4(a0, a1, a2, a3, Abase + (uint32_t)(mt * 16 * 272) + ko);
                    MMA_F16(acc[mt][0], a0, a1, a2, a3, whf[ks*2+0][0], whf[ks*2+0][1]);
                    MMA_F16(acc[mt][1], a0, a1, a2, a3, whf[ks*2+1][0], whf[ks*2+1][1]);
                }
            }

            // acc -> epi smem
#pragma unroll
            for (int mt = 0; mt < 4; mt++) {
                int r = mt * 16 + (lane >> 2);
#pragma unroll
                for (int nt = 0; nt < 2; nt++) {
                    float2 b = nt ? bb1 : bb0;
                    uint32_t cbyte = (uint32_t)((w * 16 + nt * 8 + (lane & 3) * 2) * 2);
                    half2 v0 = __floats2half2_rn(acc[mt][nt][0] + b.x, acc[mt][nt][1] + b.y);
                    half2 v1 = __floats2half2_rn(acc[mt][nt][2] + b.x, acc[mt][nt][3] + b.y);
                    *(half2*)(smem + OF_EPI + (uint32_t)r * 272 + cbyte) = v0;
                    *(half2*)(smem + OF_EPI + (uint32_t)(r + 8) * 272 + cbyte) = v1;
                }
            }
            __syncthreads();

            // coalesced STG.128
            {
                const int m0 = t * 64;
                const int rows_valid = N - m0;
#pragma unroll
                for (int p = 0; p < 4; p++) {
                    int linear = p * 4096 + tid * 16;
                    int row = linear >> 8;
                    int cb = linear & 255;
                    if (row < rows_valid)
                        *(uint4*)(dsttab + (size_t)(m0 + row) * 128 + (cb >> 1)) =
                            *(const uint4*)(smem + OF_EPI + row * 272 + cb);
                }
            }

            // publish tile completion
            __threadfence();
            __syncthreads();
            if (tid == 0)
                atomicOr(&g_s.tflag[hb][t >> 5], 1u << (t & 31));

            if (tn < ntiles) cvt_sts(it ? OF_C0 : OF_C1);
            it ^= 1;
        }
        // fall through to edge processing
    } else {
        // =================== EDGE SORT ROLE ===================
        const int ecta = bid - NODE_CTAS;
        const unsigned estart = (unsigned)(ecta * 256 + tid);
        const unsigned estride = EDGE_CTAS * 256;

        // histogram
        for (unsigned e = estart; e < (unsigned)E; e += estride) {
            unsigned row, col;
            if (is64) { row = (unsigned)ei64[e]; col = (unsigned)ei64[E + e]; }
            else      { row = (unsigned)ei32[e]; col = (unsigned)ei32[E + e]; }
            unsigned mx = row > col ? row : col;
            unsigned b = (unsigned)(((unsigned long long)mx * NBK) / (unsigned)N);
            if (b >= NBK) b = NBK - 1;
            agg_add(g_s.hist, b);
        }
        __threadfence();
        __syncthreads();
        if (tid == 0) atomicAdd(&g_s.ebar1, 1);

        // prefix by first edge CTA
        if (bid == NODE_CTAS && tid == 0) {
            while (*(volatile unsigned*)&g_s.ebar1 != EDGE_CTAS) __nanosleep(200);
            __threadfence();
            unsigned acc = 0;
            for (int b = 0; b < NBK; b++) {
                g_s.boff[b] = acc;
                g_s.bcur[b] = acc;
                acc += g_s.hist[b];
            }
            g_s.boff[NBK] = acc;
            __threadfence();
            atomicExch(&g_s.pfx, 1);
        }
        if (tid == 0) { while (*(volatile unsigned*)&g_s.pfx == 0) __nanosleep(200); }
        __syncthreads();
        __threadfence();

        // scatter
        for (unsigned e = estart; e < (unsigned)E; e += estride) {
            unsigned row, col;
            if (is64) { row = (unsigned)ei64[e]; col = (unsigned)ei64[E + e]; }
            else      { row = (unsigned)ei32[e]; col = (unsigned)ei32[E + e]; }
            unsigned mx = row > col ? row : col;
            unsigned b = (unsigned)(((unsigned long long)mx * NBK) / (unsigned)N);
            if (b >= NBK) b = NBK - 1;
            unsigned pos = agg_add(g_s.bcur, b);
            g_eord[pos] = make_uint4(row, col, e, 0);
        }
        __threadfence();
        __syncthreads();
        if (tid == 0) atomicAdd(&g_s.ebar2, 1);
    }

    // =================== EDGE PROCESSING (all CTAs) ===================
    if (tid == 0) {
        while (*(volatile unsigned*)&g_s.ebar2 != EDGE_CTAS) __nanosleep(300);
    }
    __syncthreads();
    __threadfence();

    const int gid = tid >> 4;          // 16 groups per CTA
    const int sl  = tid & 15;          // lane within group
    const float4 w2a = ((const float4*)W2)[sl * 2];
    const float4 w2b = ((const float4*)W2)[sl * 2 + 1];
    const float b2v = __ldg(b2);

    __shared__ unsigned sh_i;
    int prog = 0;                      // frontier word progress (tid 0 only)

    for (int g = 0; g < NBK; g++) {
        // wait until node frontier covers bucket g (both halves)
        if (tid == 0) {
            unsigned R = (unsigned)((((unsigned long long)(g + 1) * N) - 1) >> 6) + 1;
            if (R > (unsigned)N) R = (unsigned)N;
            unsigned Tg = (R + 63) >> 6;
            int fullw = (int)(Tg >> 5);
            unsigned rem = Tg & 31;
            volatile unsigned* f0 = g_s.tflag[0];
            volatile unsigned* f1 = g_s.tflag[1];
            while (true) {
                bool ok = true;
                while (prog < fullw) {
                    if (f0[prog] == 0xffffffffu && f1[prog] == 0xffffffffu) prog++;
                    else { ok = false; break; }
                }
                if (ok && rem) {
                    unsigned m = (1u << rem) - 1;
                    if ((f0[fullw] & m) != m || (f1[fullw] & m) != m) ok = false;
                }
                if (ok) break;
                __nanosleep(300);
            }
        }
        __syncthreads();
        __threadfence();

        const unsigned base = g_s.boff[g];
        const unsigned cnt  = g_s.boff[g + 1] - base;

        while (true) {
            if (tid == 0) sh_i = atomicAdd(&g_s.ccur[g], CH);
            __syncthreads();
            unsigned i = sh_i;
            __syncthreads();
            if (i >= cnt) break;
            unsigned csize = cnt - i;
            if (csize > CH) csize = CH;
            const unsigned start = base + i;
            const unsigned jend = (csize + 63) & ~63u;
            for (unsigned j = (unsigned)gid * 4; j < jend; j += 64) {
                uint4 o[4], av[4], bv[4];
                bool val[4];
#pragma unroll
                for (int q = 0; q < 4; q++) {
                    unsigned jj = j + q;
                    val[q] = jj < csize;
                    unsigned k = start + (val[q] ? jj : 0);
                    o[q] = g_eord[k];
                }
#pragma unroll
                for (int q = 0; q < 4; q++) {
                    av[q] = *(const uint4*)(g_A16 + (size_t)o[q].x * 128 + sl * 8);
                    bv[q] = *(const uint4*)(g_B16 + (size_t)o[q].y * 128 + sl * 8);
                }
#pragma unroll
                for (int q = 0; q < 4; q++) {
                    float s = edge_dot(av[q], bv[q], w2a, w2b);
#pragma unroll
                    for (int off = 8; off; off >>= 1)
                        s += __shfl_xor_sync(0xffffffffu, s, off);
                    if (val[q] && sl == 0) out[o[q].z] = s + b2v;
                }
            }
        }
    }
}

// ---------------------------------------------------------------------------
// Launch
// ---------------------------------------------------------------------------
extern "C" void kernel_launch(void* const* d_in, const int* in_sizes, int n_in,
                              void* d_out, int out_size)
{
    const float* z  = (const float*)d_in[0];
    const void*  ei = d_in[1];
    const float* W1 = (const float*)d_in[2];
    const float* b1 = (const float*)d_in[3];
    const float* W2 = (const float*)d_in[4];
    const float* b2 = (const float*)d_in[5];
    float* out = (float*)d_out;

    const int N = in_sizes[0] / D;   // 100000
    const int E = out_size;          // 800000

    init_kernel<<<1, 256>>>();

    cudaFuncSetAttribute(fused_kernel,
                         cudaFuncAttributeMaxDynamicSharedMemorySize, 52224);
    fused_kernel<<<TOT_CTAS, 256, 52224>>>(z, W1, b1, ei, W2, b2, out, N, E);
}

// round 11
// speedup vs baseline: 1.6307x; 1.6307x over previous
#include <cuda_runtime.h>
#include <cuda_fp16.h>
#include <stdint.h>

#define D 128
#define NMAX 100000
#define EMAX 1000000
#define WPITCH 136                   // fp16 elems per smem row (128 + 8 pad)
#define PITCHB 272                   // bytes

// ---------------------------------------------------------------------------
// Device scratch (static — no cudaMalloc allowed)
// ---------------------------------------------------------------------------
__device__ __align__(16) __half g_A16[(size_t)(NMAX + 128) * 128];
__device__ __align__(16) __half g_B16[(size_t)(NMAX + 128) * 128];
__device__ __align__(16) uint4  g_eord[EMAX];     // {row, col, e, 0} row-sorted
__device__ unsigned g_hist[1024];
__device__ unsigned g_boff[1025];
__device__ unsigned g_bcur[1024];

// ---------------------------------------------------------------------------
// PTX helpers (sm_80-era only; safe on .target sm_103)
// ---------------------------------------------------------------------------
__device__ __forceinline__ uint32_t smem_u32(const void* p) {
    uint32_t a;
    asm("{ .reg .u64 t; cvta.to.shared.u64 t, %1; cvt.u32.u64 %0, t; }"
        : "=r"(a) : "l"(p));
    return a;
}

#define LDSM_X4(r0, r1, r2, r3, addr)                                           \
    asm volatile("ldmatrix.sync.aligned.m8n8.x4.shared.b16 {%0,%1,%2,%3},[%4];" \
                 : "=r"(r0), "=r"(r1), "=r"(r2), "=r"(r3) : "r"(addr))

#define LDSM_X2(r0, r1, addr)                                                \
    asm volatile("ldmatrix.sync.aligned.m8n8.x2.shared.b16 {%0,%1},[%2];"    \
                 : "=r"(r0), "=r"(r1) : "r"(addr))

#define MMA_F16(d, a0, a1, a2, a3, b0, b1)                                   \
    asm volatile("mma.sync.aligned.m16n8k16.row.col.f32.f16.f16.f32 "        \
                 "{%0,%1,%2,%3},{%4,%5,%6,%7},{%8,%9},{%0,%1,%2,%3};"        \
                 : "+f"((d)[0]), "+f"((d)[1]), "+f"((d)[2]), "+f"((d)[3])    \
                 : "r"(a0), "r"(a1), "r"(a2), "r"(a3), "r"(b0), "r"(b1))

// warp-aggregated atomicAdd of 1 per lane, keyed by bucket b
__device__ __forceinline__ unsigned agg_add(unsigned* arr, unsigned b) {
    unsigned am = __activemask();
    unsigned mask = __match_any_sync(am, b);
    int lane = threadIdx.x & 31;
    int leader = __ffs(mask) - 1;
    unsigned base = 0;
    if (lane == leader) base = atomicAdd(arr + b, __popc(mask));
    base = __shfl_sync(mask, base, leader);
    return base + __popc(mask & ((1u << lane) - 1));
}

__device__ __forceinline__ int detect_is64(const long long* ei64, int N) {
    int is64 = 1;
#pragma unroll
    for (int i = 0; i < 8; i++) {
        long long v = __ldg(&ei64[i]);
        if (v < 0 || v >= (long long)N) is64 = 0;
    }
    return is64;
}

// ---------------------------------------------------------------------------
// Sort stage 0: zero histogram (graph-replay safe)
// ---------------------------------------------------------------------------
__global__ void zero_kernel() {
    g_hist[threadIdx.x] = 0;
}

// ---------------------------------------------------------------------------
// Sort stage 1: histogram of row>>7
// ---------------------------------------------------------------------------
__global__ void __launch_bounds__(256)
hist_kernel(const void* __restrict__ ei_raw, int E, int N) {
    const long long* ei64 = (const long long*)ei_raw;
    const int*       ei32 = (const int*)ei_raw;
    const int is64 = detect_is64(ei64, N);
    unsigned g = blockIdx.x * 256 + threadIdx.x;
    unsigned stride = gridDim.x * 256;
    for (unsigned e = g; e < (unsigned)E; e += stride) {
        unsigned row = is64 ? (unsigned)ei64[e] : (unsigned)ei32[e];
        agg_add(g_hist, row >> 7);
    }
}

// ---------------------------------------------------------------------------
// Sort stage 2: exclusive scan (one block, Hillis-Steele in smem)
// ---------------------------------------------------------------------------
__global__ void prefix_kernel(int N) {
    __shared__ unsigned s[1024];
    const int nb = (N + 127) >> 7;
    const int t = threadIdx.x;
    unsigned v = (t < nb) ? g_hist[t] : 0;
    s[t] = v;
    __syncthreads();
#pragma unroll
    for (int off = 1; off < 1024; off <<= 1) {
        unsigned x = (t >= off) ? s[t - off] : 0;
        __syncthreads();
        s[t] += x;
        __syncthreads();
    }
    unsigned excl = s[t] - v;
    if (t < nb) { g_boff[t] = excl; g_bcur[t] = excl; }
    if (t == nb - 1) g_boff[nb] = s[t];
}

// ---------------------------------------------------------------------------
// Sort stage 3: scatter {row, col, e} into row-bucketed order
// ---------------------------------------------------------------------------
__global__ void __launch_bounds__(256)
scatter_kernel(const void* __restrict__ ei_raw, int E, int N) {
    const long long* ei64 = (const long long*)ei_raw;
    const int*       ei32 = (const int*)ei_raw;
    const int is64 = detect_is64(ei64, N);
    unsigned g = blockIdx.x * 256 + threadIdx.x;
    unsigned stride = gridDim.x * 256;
    for (unsigned e = g; e < (unsigned)E; e += stride) {
        unsigned row, col;
        if (is64) { row = (unsigned)ei64[e]; col = (unsigned)ei64[E + e]; }
        else      { row = (unsigned)ei32[e]; col = (unsigned)ei32[E + e]; }
        unsigned pos = agg_add(g_bcur, row >> 7);
        g_eord[pos] = make_uint4(row, col, e, 0);
    }
}

// ---------------------------------------------------------------------------
// Node projection via mma.sync fp16 (fp32 accum) — unchanged from R9 best
// ---------------------------------------------------------------------------
__global__ void __launch_bounds__(256, 2)
node_mma_kernel(const float* __restrict__ z, const float* __restrict__ W1,
                const float* __restrict__ b1, int N)
{
    extern __shared__ char smem[];
    const uint32_t OF_C0  = 0;
    const uint32_t OF_C1  = 17408;
    const uint32_t OF_EPI = 34816;

    const uint32_t sb = smem_u32(smem);
    const int tid = threadIdx.x;
    const int w = tid >> 5;
    const int lane = tid & 31;
    const int hb = blockIdx.x & 1;
    const int tstart = blockIdx.x >> 1;
    const int ntiles = (N + 63) / 64;

    float4 rawreg[8];
    auto issue_ldg = [&](int t) {
        const int rows_valid = N - t * 64;
        const float4* src = (const float4*)(z + (size_t)t * 64 * 128);
#pragma unroll
        for (int q = 0; q < 8; q++) {
            int idx = tid + q * 256;
            int m = idx >> 5, j = idx & 31;
            rawreg[q] = (m < rows_valid) ? src[m * 32 + j]
                                         : make_float4(0.f, 0.f, 0.f, 0.f);
        }
    };
    auto cvt_sts = [&](uint32_t convoff) {
#pragma unroll
        for (int q = 0; q < 8; q++) {
            int idx = tid + q * 256;
            int m = idx >> 5, j = idx & 31;
            half2 h0 = __floats2half2_rn(rawreg[q].x, rawreg[q].y);
            half2 h1 = __floats2half2_rn(rawreg[q].z, rawreg[q].w);
            *(uint2*)(smem + convoff + (uint32_t)(m * 272 + j * 8)) =
                make_uint2(*(uint32_t*)&h0, *(uint32_t*)&h1);
        }
    };

    if (tstart < ntiles) issue_ldg(tstart);

    uint32_t whf[16][2];
    {
        const int n0 = w * 16;
        const uint32_t stg = (uint32_t)(OF_C0 + w * 2176);
        const uint32_t boffp = sb + stg
            + (uint32_t)((lane & 7) * 272 + ((lane >> 3) & 1) * 16);
#pragma unroll
        for (int half8 = 0; half8 < 2; half8++) {
#pragma unroll
            for (int q = 0; q < 32; q++) {
                int idx = lane + q * 32;
                int r = idx & 7, k = idx >> 3;
                float x = W1[(size_t)(hb * 128 + k) * 128 + n0 + half8 * 8 + r];
                *(__half*)(smem + stg + r * 272 + k * 2) = __float2half_rn(x);
            }
            __syncwarp();
#pragma unroll
            for (int ks = 0; ks < 8; ks++)
                LDSM_X2(whf[ks * 2 + half8][0], whf[ks * 2 + half8][1],
                        boffp + (uint32_t)(ks * 32));
            __syncwarp();
        }
    }
    __syncthreads();

    if (tstart < ntiles) cvt_sts(OF_C0);

    float2 bb0 = make_float2(0.f, 0.f), bb1 = bb0;
    if (hb) {
        int c = w * 16 + (lane & 3) * 2;
        bb0 = *(const float2*)(b1 + c);
        bb1 = *(const float2*)(b1 + c + 8);
    }
    __half* dsttab = hb ? g_B16 : g_A16;
    const uint32_t a_off = (uint32_t)((lane & 15) * WPITCH + (lane >> 4) * 8) * 2;
    const uint32_t Ah = sb + OF_C0 + a_off;

    int it = 0;
    for (int t = tstart; t < ntiles; t += 148) {
        const int tn = t + 148;
        __syncthreads();
        if (tn < ntiles) issue_ldg(tn);

        float acc[4][2][4];
#pragma unroll
        for (int mt = 0; mt < 4; mt++)
#pragma unroll
            for (int nt = 0; nt < 2; nt++)
#pragma unroll
                for (int q = 0; q < 4; q++) acc[mt][nt][q] = 0.f;

        const uint32_t Abase = Ah + (uint32_t)(it * 17408);
#pragma unroll
        for (int ks = 0; ks < 8; ks++) {
            const uint32_t ko = (uint32_t)ks * 32;
#pragma unroll
            for (int mt = 0; mt < 4; mt++) {
                uint32_t a0, a1, a2, a3;
                LDSM_X4(a0, a1, a2, a3, Abase + (uint32_t)(mt * 16 * 272) + ko);
                MMA_F16(acc[mt][0], a0, a1, a2, a3, whf[ks*2+0][0], whf[ks*2+0][1]);
                MMA_F16(acc[mt][1], a0, a1, a2, a3, whf[ks*2+1][0], whf[ks*2+1][1]);
            }
        }

#pragma unroll
        for (int mt = 0; mt < 4; mt++) {
            int r = mt * 16 + (lane >> 2);
#pragma unroll
            for (int nt = 0; nt < 2; nt++) {
                float2 b = nt ? bb1 : bb0;
                uint32_t cbyte = (uint32_t)((w * 16 + nt * 8 + (lane & 3) * 2) * 2);
                half2 v0 = __floats2half2_rn(acc[mt][nt][0] + b.x, acc[mt][nt][1] + b.y);
                half2 v1 = __floats2half2_rn(acc[mt][nt][2] + b.x, acc[mt][nt][3] + b.y);
                *(half2*)(smem + OF_EPI + (uint32_t)r * 272 + cbyte) = v0;
                *(half2*)(smem + OF_EPI + (uint32_t)(r + 8) * 272 + cbyte) = v1;
            }
        }
        __syncthreads();

        {
            const int m0 = t * 64;
            const int rows_valid = N - m0;
#pragma unroll
            for (int p = 0; p < 4; p++) {
                int linear = p * 4096 + tid * 16;
                int row = linear >> 8;
                int cb = linear & 255;
                if (row < rows_valid)
                    *(uint4*)(dsttab + (size_t)(m0 + row) * 128 + (cb >> 1)) =
                        *(const uint4*)(smem + OF_EPI + row * 272 + cb);
            }
        }

        if (tn < ntiles) cvt_sts(it ? OF_C0 : OF_C1);
        it ^= 1;
    }
}

// ---------------------------------------------------------------------------
// Edge pass over row-sorted edges: A gathers hit L1 (~8x reuse per node)
// ---------------------------------------------------------------------------
__device__ __forceinline__ float edge_dot(uint4 a4, uint4 b4,
                                          float4 w2a, float4 w2b) {
    const half2 z2 = __floats2half2_rn(0.f, 0.f);
    half2 h0 = __hmax2(__hadd2(*(half2*)&a4.x, *(half2*)&b4.x), z2);
    half2 h1 = __hmax2(__hadd2(*(half2*)&a4.y, *(half2*)&b4.y), z2);
    half2 h2 = __hmax2(__hadd2(*(half2*)&a4.z, *(half2*)&b4.z), z2);
    half2 h3 = __hmax2(__hadd2(*(half2*)&a4.w, *(half2*)&b4.w), z2);
    float2 f0 = __half22float2(h0);
    float2 f1 = __half22float2(h1);
    float2 f2 = __half22float2(h2);
    float2 f3 = __half22float2(h3);
    return f0.x * w2a.x + f0.y * w2a.y + f1.x * w2a.z + f1.y * w2a.w
         + f2.x * w2b.x + f2.y * w2b.y + f3.x * w2b.z + f3.y * w2b.w;
}

__global__ void __launch_bounds__(256)
edge_kernel(const float* __restrict__ W2, const float* __restrict__ b2,
            float* __restrict__ out, int E)
{
    const int tid = threadIdx.x;
    const int gid = tid >> 4;          // 16 groups per CTA
    const int sl  = tid & 15;

    const float4 w2a = ((const float4*)W2)[sl * 2];
    const float4 w2b = ((const float4*)W2)[sl * 2 + 1];
    const float b2v = __ldg(b2);

    const int nch = (E + 2047) >> 11;
    for (int c = blockIdx.x; c < nch; c += gridDim.x) {
        const unsigned start = (unsigned)c << 11;
        const unsigned csize = min(2048u, (unsigned)E - start);
        const unsigned jend = (csize + 63) & ~63u;
        for (unsigned j = (unsigned)gid * 4; j < jend; j += 64) {
            uint4 o[4], av[4], bv[4];
            bool val[4];
#pragma unroll
            for (int q = 0; q < 4; q++) {
                unsigned jj = j + q;
                val[q] = jj < csize;
                o[q] = g_eord[start + (val[q] ? jj : 0)];
            }
#pragma unroll
            for (int q = 0; q < 4; q++) {
                av[q] = *(const uint4*)(g_A16 + (size_t)o[q].x * 128 + sl * 8);
                bv[q] = *(const uint4*)(g_B16 + (size_t)o[q].y * 128 + sl * 8);
            }
#pragma unroll
            for (int q = 0; q < 4; q++) {
                float s = edge_dot(av[q], bv[q], w2a, w2b);
#pragma unroll
                for (int off = 8; off; off >>= 1)
                    s += __shfl_xor_sync(0xffffffffu, s, off);
                if (val[q] && sl == 0) out[o[q].z] = s + b2v;
            }
        }
    }
}

// ---------------------------------------------------------------------------
// Launch
// ---------------------------------------------------------------------------
extern "C" void kernel_launch(void* const* d_in, const int* in_sizes, int n_in,
                              void* d_out, int out_size)
{
    const float* z  = (const float*)d_in[0];
    const void*  ei = d_in[1];
    const float* W1 = (const float*)d_in[2];
    const float* b1 = (const float*)d_in[3];
    const float* W2 = (const float*)d_in[4];
    const float* b2 = (const float*)d_in[5];
    float* out = (float*)d_out;

    const int N = in_sizes[0] / D;   // 100000
    const int E = out_size;          // 800000

    zero_kernel<<<1, 1024>>>();
    hist_kernel<<<592, 256>>>(ei, E, N);
    prefix_kernel<<<1, 1024>>>(N);
    scatter_kernel<<<592, 256>>>(ei, E, N);

    cudaFuncSetAttribute(node_mma_kernel,
                         cudaFuncAttributeMaxDynamicSharedMemorySize, 52224);
    node_mma_kernel<<<296, 256, 52224>>>(z, W1, b1, N);

    edge_kernel<<<1184, 256>>>(W2, b2, out, E);
}

// round 12
// speedup vs baseline: 3.0491x; 1.8698x over previous
#include <cuda_runtime.h>
#include <cuda_fp16.h>
#include <stdint.h>

#define D 128
#define NMAX 100000
#define EMAX 1000000
#define WPITCH 136                   // fp16 elems per smem row (128 + 8 pad)
#define PITCHB 272                   // bytes

#define TOT_CTAS 296
#define NODE_CTAS 264
#define HALF_CTAS 132
#define SORT_CTAS 32
#define NB 1024                      // bucket slots (row>>7 -> 782 used)

// ---------------------------------------------------------------------------
// Device scratch (static — no cudaMalloc allowed)
// ---------------------------------------------------------------------------
__device__ __align__(16) __half g_A16[(size_t)(NMAX + 128) * 128];
__device__ __align__(16) __half g_B16[(size_t)(NMAX + 128) * 128];
__device__ __align__(16) uint4  g_eord[EMAX];     // {row, col, e, 0} row-sorted
__device__ unsigned g_hist[NB];
__device__ unsigned g_bcur[NB];
__device__ unsigned g_sync[4];       // [0]=ebar1  [1]=pfx

// ---------------------------------------------------------------------------
// PTX helpers (sm_80-era only; safe on .target sm_103)
// ---------------------------------------------------------------------------
__device__ __forceinline__ uint32_t smem_u32(const void* p) {
    uint32_t a;
    asm("{ .reg .u64 t; cvta.to.shared.u64 t, %1; cvt.u32.u64 %0, t; }"
        : "=r"(a) : "l"(p));
    return a;
}

#define LDSM_X4(r0, r1, r2, r3, addr)                                           \
    asm volatile("ldmatrix.sync.aligned.m8n8.x4.shared.b16 {%0,%1,%2,%3},[%4];" \
                 : "=r"(r0), "=r"(r1), "=r"(r2), "=r"(r3) : "r"(addr))

#define LDSM_X2(r0, r1, addr)                                                \
    asm volatile("ldmatrix.sync.aligned.m8n8.x2.shared.b16 {%0,%1},[%2];"    \
                 : "=r"(r0), "=r"(r1) : "r"(addr))

#define MMA_F16(d, a0, a1, a2, a3, b0, b1)                                   \
    asm volatile("mma.sync.aligned.m16n8k16.row.col.f32.f16.f16.f32 "        \
                 "{%0,%1,%2,%3},{%4,%5,%6,%7},{%8,%9},{%0,%1,%2,%3};"        \
                 : "+f"((d)[0]), "+f"((d)[1]), "+f"((d)[2]), "+f"((d)[3])    \
                 : "r"(a0), "r"(a1), "r"(a2), "r"(a3), "r"(b0), "r"(b1))

__device__ __forceinline__ int detect_is64(const long long* ei64, int N) {
    int is64 = 1;
#pragma unroll
    for (int i = 0; i < 8; i++) {
        long long v = __ldg(&ei64[i]);
        if (v < 0 || v >= (long long)N) is64 = 0;
    }
    return is64;
}

// ---------------------------------------------------------------------------
// zero: reset hist + sync words each launch (graph-replay safe)
// ---------------------------------------------------------------------------
__global__ void zero_kernel() {
    if (threadIdx.x < NB) g_hist[threadIdx.x] = 0;
    if (threadIdx.x < 4)  g_sync[threadIdx.x] = 0;
}

// ---------------------------------------------------------------------------
// fused kernel: node producers (bid<264) + independent sort group (bid>=264)
// The two groups NEVER wait on each other.
// ---------------------------------------------------------------------------
__global__ void __launch_bounds__(256, 2)
fused_kernel(const float* __restrict__ z, const float* __restrict__ W1,
             const float* __restrict__ b1, const void* __restrict__ ei_raw,
             int N, int E)
{
    extern __shared__ char smem[];
    const int tid = threadIdx.x;
    const int bid = blockIdx.x;

    if (bid < NODE_CTAS) {
        // =================== NODE ROLE (R9 pipeline) ===================
        const uint32_t OF_C0  = 0;
        const uint32_t OF_C1  = 17408;
        const uint32_t OF_EPI = 34816;
        const uint32_t sb = smem_u32(smem);
        const int w = tid >> 5;
        const int lane = tid & 31;
        const int hb = bid & 1;
        const int tstart = bid >> 1;           // 0..131
        const int ntiles = (N + 63) / 64;

        float4 rawreg[8];
        auto issue_ldg = [&](int t) {
            const int rows_valid = N - t * 64;
            const float4* src = (const float4*)(z + (size_t)t * 64 * 128);
#pragma unroll
            for (int q = 0; q < 8; q++) {
                int idx = tid + q * 256;
                int m = idx >> 5, j = idx & 31;
                rawreg[q] = (m < rows_valid) ? src[m * 32 + j]
                                             : make_float4(0.f, 0.f, 0.f, 0.f);
            }
        };
        auto cvt_sts = [&](uint32_t convoff) {
#pragma unroll
            for (int q = 0; q < 8; q++) {
                int idx = tid + q * 256;
                int m = idx >> 5, j = idx & 31;
                half2 h0 = __floats2half2_rn(rawreg[q].x, rawreg[q].y);
                half2 h1 = __floats2half2_rn(rawreg[q].z, rawreg[q].w);
                *(uint2*)(smem + convoff + (uint32_t)(m * 272 + j * 8)) =
                    make_uint2(*(uint32_t*)&h0, *(uint32_t*)&h1);
            }
        };

        if (tstart < ntiles) issue_ldg(tstart);

        uint32_t whf[16][2];
        {
            const int n0 = w * 16;
            const uint32_t stg = (uint32_t)(OF_C0 + w * 2176);
            const uint32_t boffp = sb + stg
                + (uint32_t)((lane & 7) * 272 + ((lane >> 3) & 1) * 16);
#pragma unroll
            for (int half8 = 0; half8 < 2; half8++) {
#pragma unroll
                for (int q = 0; q < 32; q++) {
                    int idx = lane + q * 32;
                    int r = idx & 7, k = idx >> 3;
                    float x = W1[(size_t)(hb * 128 + k) * 128 + n0 + half8 * 8 + r];
                    *(__half*)(smem + stg + r * 272 + k * 2) = __float2half_rn(x);
                }
                __syncwarp();
#pragma unroll
                for (int ks = 0; ks < 8; ks++)
                    LDSM_X2(whf[ks * 2 + half8][0], whf[ks * 2 + half8][1],
                            boffp + (uint32_t)(ks * 32));
                __syncwarp();
            }
        }
        __syncthreads();

        if (tstart < ntiles) cvt_sts(OF_C0);

        float2 bb0 = make_float2(0.f, 0.f), bb1 = bb0;
        if (hb) {
            int c = w * 16 + (lane & 3) * 2;
            bb0 = *(const float2*)(b1 + c);
            bb1 = *(const float2*)(b1 + c + 8);
        }
        __half* dsttab = hb ? g_B16 : g_A16;
        const uint32_t a_off = (uint32_t)((lane & 15) * WPITCH + (lane >> 4) * 8) * 2;
        const uint32_t Ah = sb + OF_C0 + a_off;

        int it = 0;
        for (int t = tstart; t < ntiles; t += HALF_CTAS) {
            const int tn = t + HALF_CTAS;
            __syncthreads();
            if (tn < ntiles) issue_ldg(tn);

            float acc[4][2][4];
#pragma unroll
            for (int mt = 0; mt < 4; mt++)
#pragma unroll
                for (int nt = 0; nt < 2; nt++)
#pragma unroll
                    for (int q = 0; q < 4; q++) acc[mt][nt][q] = 0.f;

            const uint32_t Abase = Ah + (uint32_t)(it * 17408);
#pragma unroll
            for (int ks = 0; ks < 8; ks++) {
                const uint32_t ko = (uint32_t)ks * 32;
#pragma unroll
                for (int mt = 0; mt < 4; mt++) {
                    uint32_t a0, a1, a2, a3;
                    LDSM_X4(a0, a1, a2, a3, Abase + (uint32_t)(mt * 16 * 272) + ko);
                    MMA_F16(acc[mt][0], a0, a1, a2, a3, whf[ks*2+0][0], whf[ks*2+0][1]);
                    MMA_F16(acc[mt][1], a0, a1, a2, a3, whf[ks*2+1][0], whf[ks*2+1][1]);
                }
            }

#pragma unroll
            for (int mt = 0; mt < 4; mt++) {
                int r = mt * 16 + (lane >> 2);
#pragma unroll
                for (int nt = 0; nt < 2; nt++) {
                    float2 b = nt ? bb1 : bb0;
                    uint32_t cbyte = (uint32_t)((w * 16 + nt * 8 + (lane & 3) * 2) * 2);
                    half2 v0 = __floats2half2_rn(acc[mt][nt][0] + b.x, acc[mt][nt][1] + b.y);
                    half2 v1 = __floats2half2_rn(acc[mt][nt][2] + b.x, acc[mt][nt][3] + b.y);
                    *(half2*)(smem + OF_EPI + (uint32_t)r * 272 + cbyte) = v0;
                    *(half2*)(smem + OF_EPI + (uint32_t)(r + 8) * 272 + cbyte) = v1;
                }
            }
            __syncthreads();

            {
                const int m0 = t * 64;
                const int rows_valid = N - m0;
#pragma unroll
                for (int p = 0; p < 4; p++) {
                    int linear = p * 4096 + tid * 16;
                    int row = linear >> 8;
                    int cb = linear & 255;
                    if (row < rows_valid)
                        *(uint4*)(dsttab + (size_t)(m0 + row) * 128 + (cb >> 1)) =
                            *(const uint4*)(smem + OF_EPI + row * 272 + cb);
                }
            }

            if (tn < ntiles) cvt_sts(it ? OF_C0 : OF_C1);
            it ^= 1;
        }
        return;
    }

    // =================== SORT ROLE (CTA-local aggregation) ===================
    {
        const int sid = bid - NODE_CTAS;       // 0..31
        const long long* ei64 = (const long long*)ei_raw;
        const int*       ei32 = (const int*)ei_raw;
        const int is64 = detect_is64(ei64, N);

        unsigned* lh = (unsigned*)smem;        // NB counters

        // ---- phase 1: histogram (CTA-local smem, then per-bucket global add)
        for (int b = tid; b < NB; b += 256) lh[b] = 0;
        __syncthreads();
        {
            unsigned g = (unsigned)(sid * 256 + tid);
            unsigned stride = SORT_CTAS * 256;
            for (unsigned e = g; e < (unsigned)E; e += stride) {
                unsigned row = is64 ? (unsigned)ei64[e] : (unsigned)ei32[e];
                atomicAdd(&lh[row >> 7], 1u);
            }
        }
        __syncthreads();
        for (int b = tid; b < NB; b += 256) {
            unsigned c = lh[b];
            if (c) atomicAdd(&g_hist[b], c);
        }
        __threadfence();
        __syncthreads();
        if (tid == 0) atomicAdd(&g_sync[0], 1);

        // ---- phase 2: exclusive scan by sort CTA 0 -> g_bcur
        if (sid == 0) {
            if (tid == 0)
                while (*(volatile unsigned*)&g_sync[0] != SORT_CTAS) __nanosleep(200);
            __syncthreads();
            __threadfence();

            unsigned* P = (unsigned*)smem + NB;  // 256 partials
            unsigned v[4], s[4];
#pragma unroll
            for (int i = 0; i < 4; i++) v[i] = g_hist[tid * 4 + i];
            s[0] = v[0];
#pragma unroll
            for (int i = 1; i < 4; i++) s[i] = s[i - 1] + v[i];
            P[tid] = s[3];
            __syncthreads();
#pragma unroll
            for (int off = 1; off < 256; off <<= 1) {
                unsigned x = (tid >= off) ? P[tid - off] : 0;
                __syncthreads();
                P[tid] += x;
                __syncthreads();
            }
            unsigned base = P[tid] - s[3];
            g_bcur[tid * 4 + 0] = base;
            g_bcur[tid * 4 + 1] = base + s[0];
            g_bcur[tid * 4 + 2] = base + s[1];
            g_bcur[tid * 4 + 3] = base + s[2];
            __threadfence();
            __syncthreads();
            if (tid == 0) atomicExch(&g_sync[1], 1);
        } else {
            if (tid == 0)
                while (*(volatile unsigned*)&g_sync[1] == 0) __nanosleep(200);
            __syncthreads();
        }
        __threadfence();

        // ---- phase 3: scatter, CTA-local aggregation over blocked chunk
        const unsigned chunkE = ((unsigned)E + SORT_CTAS - 1) / SORT_CTAS;
        const unsigned lo = (unsigned)sid * chunkE;
        const unsigned hi = min((unsigned)E, lo + chunkE);

        for (int b = tid; b < NB; b += 256) lh[b] = 0;
        __syncthreads();
        for (unsigned e = lo + tid; e < hi; e += 256) {
            unsigned row = is64 ? (unsigned)ei64[e] : (unsigned)ei32[e];
            atomicAdd(&lh[row >> 7], 1u);
        }
        __syncthreads();
        for (int b = tid; b < NB; b += 256) {
            unsigned c = lh[b];
            if (c) lh[b] = atomicAdd(&g_bcur[b], c);   // reserve segment
        }
        __syncthreads();
        for (unsigned e = lo + tid; e < hi; e += 256) {
            unsigned row, col;
            if (is64) { row = (unsigned)ei64[e]; col = (unsigned)ei64[E + e]; }
            else      { row = (unsigned)ei32[e]; col = (unsigned)ei32[E + e]; }
            unsigned pos = atomicAdd(&lh[row >> 7], 1u);
            g_eord[pos] = make_uint4(row, col, e, 0);
        }
    }
}

// ---------------------------------------------------------------------------
// Edge pass over row-sorted edges: A rows hit L1 (~8x reuse per chunk)
// ---------------------------------------------------------------------------
__device__ __forceinline__ float edge_dot(uint4 a4, uint4 b4,
                                          float4 w2a, float4 w2b) {
    const half2 z2 = __floats2half2_rn(0.f, 0.f);
    half2 h0 = __hmax2(__hadd2(*(half2*)&a4.x, *(half2*)&b4.x), z2);
    half2 h1 = __hmax2(__hadd2(*(half2*)&a4.y, *(half2*)&b4.y), z2);
    half2 h2 = __hmax2(__hadd2(*(half2*)&a4.z, *(half2*)&b4.z), z2);
    half2 h3 = __hmax2(__hadd2(*(half2*)&a4.w, *(half2*)&b4.w), z2);
    float2 f0 = __half22float2(h0);
    float2 f1 = __half22float2(h1);
    float2 f2 = __half22float2(h2);
    float2 f3 = __half22float2(h3);
    return f0.x * w2a.x + f0.y * w2a.y + f1.x * w2a.z + f1.y * w2a.w
         + f2.x * w2b.x + f2.y * w2b.y + f3.x * w2b.z + f3.y * w2b.w;
}

__global__ void __launch_bounds__(256)
edge_kernel(const float* __restrict__ W2, const float* __restrict__ b2,
            float* __restrict__ out, int E)
{
    const int tid = threadIdx.x;
    const int gid = tid >> 4;
    const int sl  = tid & 15;

    const float4 w2a = ((const float4*)W2)[sl * 2];
    const float4 w2b = ((const float4*)W2)[sl * 2 + 1];
    const float b2v = __ldg(b2);

    const int nch = (E + 2047) >> 11;
    for (int c = blockIdx.x; c < nch; c += gridDim.x) {
        const unsigned start = (unsigned)c << 11;
        const unsigned csize = min(2048u, (unsigned)E - start);
        const unsigned jend = (csize + 63) & ~63u;
        for (unsigned j = (unsigned)gid * 4; j < jend; j += 64) {
            uint4 o[4], av[4], bv[4];
            bool val[4];
#pragma unroll
            for (int q = 0; q < 4; q++) {
                unsigned jj = j + q;
                val[q] = jj < csize;
                o[q] = g_eord[start + (val[q] ? jj : 0)];
            }
#pragma unroll
            for (int q = 0; q < 4; q++) {
                av[q] = *(const uint4*)(g_A16 + (size_t)o[q].x * 128 + sl * 8);
                bv[q] = *(const uint4*)(g_B16 + (size_t)o[q].y * 128 + sl * 8);
            }
#pragma unroll
            for (int q = 0; q < 4; q++) {
                float s = edge_dot(av[q], bv[q], w2a, w2b);
#pragma unroll
                for (int off = 8; off; off >>= 1)
                    s += __shfl_xor_sync(0xffffffffu, s, off);
                if (val[q] && sl == 0) out[o[q].z] = s + b2v;
            }
        }
    }
}

// ---------------------------------------------------------------------------
// Launch
// ---------------------------------------------------------------------------
extern "C" void kernel_launch(void* const* d_in, const int* in_sizes, int n_in,
                              void* d_out, int out_size)
{
    const float* z  = (const float*)d_in[0];
    const void*  ei = d_in[1];
    const float* W1 = (const float*)d_in[2];
    const float* b1 = (const float*)d_in[3];
    const float* W2 = (const float*)d_in[4];
    const float* b2 = (const float*)d_in[5];
    float* out = (float*)d_out;

    const int N = in_sizes[0] / D;   // 100000
    const int E = out_size;          // 800000

    zero_kernel<<<1, 1024>>>();

    cudaFuncSetAttribute(fused_kernel,
                         cudaFuncAttributeMaxDynamicSharedMemorySize, 52224);
    fused_kernel<<<TOT_CTAS, 256, 52224>>>(z, W1, b1, ei, N, E);

    const int nch = (E + 2047) >> 11;
    edge_kernel<<<nch, 256>>>(W2, b2, out, E);
}

// round 13
// speedup vs baseline: 5.5050x; 1.8055x over previous
#include <cuda_runtime.h>
#include <cuda_fp16.h>
#include <stdint.h>

#define D 128
#define NMAX 100000
#define WPITCH 136                   // fp16 elems per smem row (128 + 8 pad)
#define PITCHB 272                   // bytes

// ---------------------------------------------------------------------------
// Device scratch (static — no cudaMalloc allowed)
// ---------------------------------------------------------------------------
__device__ __align__(16) __half g_A16[(size_t)(NMAX + 128) * 128];  // z@W1[:128]
__device__ __align__(16) __half g_B16[(size_t)(NMAX + 128) * 128];  // z@W1[128:]+b1

// ---------------------------------------------------------------------------
// PTX helpers (sm_80-era only; safe on .target sm_103)
// ---------------------------------------------------------------------------
__device__ __forceinline__ uint32_t smem_u32(const void* p) {
    uint32_t a;
    asm("{ .reg .u64 t; cvta.to.shared.u64 t, %1; cvt.u32.u64 %0, t; }"
        : "=r"(a) : "l"(p));
    return a;
}

#define LDSM_X4(r0, r1, r2, r3, addr)                                           \
    asm volatile("ldmatrix.sync.aligned.m8n8.x4.shared.b16 {%0,%1,%2,%3},[%4];" \
                 : "=r"(r0), "=r"(r1), "=r"(r2), "=r"(r3) : "r"(addr))

#define LDSM_X2(r0, r1, addr)                                                \
    asm volatile("ldmatrix.sync.aligned.m8n8.x2.shared.b16 {%0,%1},[%2];"    \
                 : "=r"(r0), "=r"(r1) : "r"(addr))

#define MMA_F16(d, a0, a1, a2, a3, b0, b1)                                   \
    asm volatile("mma.sync.aligned.m16n8k16.row.col.f32.f16.f16.f32 "        \
                 "{%0,%1,%2,%3},{%4,%5,%6,%7},{%8,%9},{%0,%1,%2,%3};"        \
                 : "+f"((d)[0]), "+f"((d)[1]), "+f"((d)[2]), "+f"((d)[3])    \
                 : "r"(a0), "r"(a1), "r"(a2), "r"(a3), "r"(b0), "r"(b1))

// ---------------------------------------------------------------------------
// Node projection via mma.sync fp16 (fp32 accum), single pass:
//   A = z16 @ W16[:128],  B = z16 @ W16[128:] + b1
// 296 CTAs x 256 thr, 2 CTAs/SM. hb = bid&1 selects table; 64-row tiles,
// stride 148. Register-staged LDG pipeline; software-pipelined LDSM;
// smem-staged coalesced epilogue.
// SMEM: conv0 17408 | conv1 17408 | epi 17408 = 52224 B
// ---------------------------------------------------------------------------
__global__ void __launch_bounds__(256, 2)
node_mma_kernel(const float* __restrict__ z, const float* __restrict__ W1,
                const float* __restrict__ b1, int N)
{
    extern __shared__ char smem[];
    const uint32_t OF_C0  = 0;
    const uint32_t OF_C1  = 17408;
    const uint32_t OF_EPI = 34816;

    const uint32_t sb = smem_u32(smem);
    const int tid = threadIdx.x;
    const int w = tid >> 5;
    const int lane = tid & 31;
    const int hb = blockIdx.x & 1;
    const int tstart = blockIdx.x >> 1;
    const int ntiles = (N + 63) / 64;

    float4 rawreg[8];
    auto issue_ldg = [&](int t) {
        const int rows_valid = N - t * 64;
        const float4* src = (const float4*)(z + (size_t)t * 64 * 128);
#pragma unroll
        for (int q = 0; q < 8; q++) {
            int idx = tid + q * 256;
            int m = idx >> 5, j = idx & 31;
            rawreg[q] = (m < rows_valid) ? src[m * 32 + j]
                                         : make_float4(0.f, 0.f, 0.f, 0.f);
        }
    };
    auto cvt_sts = [&](uint32_t convoff) {
#pragma unroll
        for (int q = 0; q < 8; q++) {
            int idx = tid + q * 256;
            int m = idx >> 5, j = idx & 31;
            half2 h0 = __floats2half2_rn(rawreg[q].x, rawreg[q].y);
            half2 h1 = __floats2half2_rn(rawreg[q].z, rawreg[q].w);
            *(uint2*)(smem + convoff + (uint32_t)(m * 272 + j * 8)) =
                make_uint2(*(uint32_t*)&h0, *(uint32_t*)&h1);
        }
    };

    if (tstart < ntiles) issue_ldg(tstart);

    // ---- W1 -> fp16 fragments in registers (16 cols per warp) ----
    uint32_t whf[16][2];
    {
        const int n0 = w * 16;
        const uint32_t stg = (uint32_t)(OF_C0 + w * 2176);   // 8 rows x 272B
        const uint32_t boffp = sb + stg
            + (uint32_t)((lane & 7) * 272 + ((lane >> 3) & 1) * 16);
#pragma unroll
        for (int half8 = 0; half8 < 2; half8++) {
#pragma unroll
            for (int q = 0; q < 32; q++) {
                int idx = lane + q * 32;
                int r = idx & 7, k = idx >> 3;
                float x = W1[(size_t)(hb * 128 + k) * 128 + n0 + half8 * 8 + r];
                *(__half*)(smem + stg + r * 272 + k * 2) = __float2half_rn(x);
            }
            __syncwarp();
#pragma unroll
            for (int ks = 0; ks < 8; ks++)
                LDSM_X2(whf[ks * 2 + half8][0], whf[ks * 2 + half8][1],
                        boffp + (uint32_t)(ks * 32));
            __syncwarp();
        }
    }
    __syncthreads();

    if (tstart < ntiles) cvt_sts(OF_C0);

    float2 bb0 = make_float2(0.f, 0.f), bb1 = bb0;
    if (hb) {
        int c = w * 16 + (lane & 3) * 2;
        bb0 = *(const float2*)(b1 + c);
        bb1 = *(const float2*)(b1 + c + 8);
    }
    __half* dsttab = hb ? g_B16 : g_A16;
    const uint32_t a_off = (uint32_t)((lane & 15) * WPITCH + (lane >> 4) * 8) * 2;
    const uint32_t Ah = sb + OF_C0 + a_off;

    int it = 0;
    for (int t = tstart; t < ntiles; t += 148) {
        const int tn = t + 148;
        __syncthreads();
        if (tn < ntiles) issue_ldg(tn);

        float acc[4][2][4];
#pragma unroll
        for (int mt = 0; mt < 4; mt++)
#pragma unroll
            for (int nt = 0; nt < 2; nt++)
#pragma unroll
                for (int q = 0; q < 4; q++) acc[mt][nt][q] = 0.f;

        // ---- MMA over flattened 32 steps (s = ks*4 + mt), LDSM dbl-buffered
        const uint32_t Abase = Ah + (uint32_t)(it * 17408);
        uint32_t ca0, ca1, ca2, ca3;       // current fragments
        uint32_t na0, na1, na2, na3;       // next fragments
        LDSM_X4(ca0, ca1, ca2, ca3, Abase);   // s = 0
#pragma unroll
        for (int s = 0; s < 32; s++) {
            if (s < 31) {
                const int sn = s + 1;
                const uint32_t addr = Abase
                    + (uint32_t)((sn & 3) * 16 * 272 + (sn >> 2) * 32);
                LDSM_X4(na0, na1, na2, na3, addr);
            }
            const int ks = s >> 2, mt = s & 3;
            MMA_F16(acc[mt][0], ca0, ca1, ca2, ca3, whf[ks*2+0][0], whf[ks*2+0][1]);
            MMA_F16(acc[mt][1], ca0, ca1, ca2, ca3, whf[ks*2+1][0], whf[ks*2+1][1]);
            ca0 = na0; ca1 = na1; ca2 = na2; ca3 = na3;
        }

        // ---- Epilogue: acc -> epi smem (conflict-free, pitch 272) ----
#pragma unroll
        for (int mt = 0; mt < 4; mt++) {
            int r = mt * 16 + (lane >> 2);
#pragma unroll
            for (int nt = 0; nt < 2; nt++) {
                float2 b = nt ? bb1 : bb0;
                uint32_t cbyte = (uint32_t)((w * 16 + nt * 8 + (lane & 3) * 2) * 2);
                half2 v0 = __floats2half2_rn(acc[mt][nt][0] + b.x, acc[mt][nt][1] + b.y);
                half2 v1 = __floats2half2_rn(acc[mt][nt][2] + b.x, acc[mt][nt][3] + b.y);
                *(half2*)(smem + OF_EPI + (uint32_t)r * 272 + cbyte) = v0;
                *(half2*)(smem + OF_EPI + (uint32_t)(r + 8) * 272 + cbyte) = v1;
            }
        }
        __syncthreads();

        // ---- Coalesced STG.128: 64 rows x 256 B ----
        {
            const int m0 = t * 64;
            const int rows_valid = N - m0;
#pragma unroll
            for (int p = 0; p < 4; p++) {
                int linear = p * 4096 + tid * 16;
                int row = linear >> 8;
                int cb = linear & 255;
                if (row < rows_valid)
                    *(uint4*)(dsttab + (size_t)(m0 + row) * 128 + (cb >> 1)) =
                        *(const uint4*)(smem + OF_EPI + row * 272 + cb);
            }
        }

        if (tn < ntiles) cvt_sts(it ? OF_C0 : OF_C1);
        it ^= 1;
    }
}

// ---------------------------------------------------------------------------
// Edge pass: out[e] = relu(A16[row] + B16[col]) . W2 + b2
// HADD2+HMAX2 add/relu, fp32 dot. 16 lanes/edge, 2-pair unroll.
// At the LTS service floor; indices read as 32-bit low words in i64 mode.
// ---------------------------------------------------------------------------
__device__ __forceinline__ float edge_dot(uint4 a4, uint4 b4,
                                          float4 w2a, float4 w2b) {
    const half2 z2 = __floats2half2_rn(0.f, 0.f);
    half2 h0 = __hmax2(__hadd2(*(half2*)&a4.x, *(half2*)&b4.x), z2);
    half2 h1 = __hmax2(__hadd2(*(half2*)&a4.y, *(half2*)&b4.y), z2);
    half2 h2 = __hmax2(__hadd2(*(half2*)&a4.z, *(half2*)&b4.z), z2);
    half2 h3 = __hmax2(__hadd2(*(half2*)&a4.w, *(half2*)&b4.w), z2);
    float2 f0 = __half22float2(h0);
    float2 f1 = __half22float2(h1);
    float2 f2 = __half22float2(h2);
    float2 f3 = __half22float2(h3);
    return f0.x * w2a.x + f0.y * w2a.y + f1.x * w2a.z + f1.y * w2a.w
         + f2.x * w2b.x + f2.y * w2b.y + f3.x * w2b.z + f3.y * w2b.w;
}

__global__ void __launch_bounds__(256)
edge_kernel(const void* __restrict__ ei_raw,
            const float* __restrict__ W2,
            const float* __restrict__ b2,
            float* __restrict__ out, int E, int N)
{
    const long long* ei64 = (const long long*)ei_raw;
    const int*       ei32 = (const int*)ei_raw;

    int is64 = 1;
#pragma unroll
    for (int i = 0; i < 8; i++) {
        long long v = __ldg(&ei64[i]);
        if (v < 0 || v >= (long long)N) is64 = 0;
    }

    const int lane = threadIdx.x & 31;
    const int sub = lane >> 4;     // which edge of the pair
    const int sl  = lane & 15;     // lane within edge (8 dims)

    const float4 w2a = ((const float4*)W2)[sl * 2];
    const float4 w2b = ((const float4*)W2)[sl * 2 + 1];
    const float b2v = __ldg(b2);

    const int warp = (blockIdx.x * 256 + threadIdx.x) >> 5;
    const int nwarp = (gridDim.x * 256) >> 5;
    const int npairs = (E + 1) >> 1;

    for (int p = warp; p < npairs; p += 2 * nwarp) {
        const int pB = p + nwarp;
        const int e1 = p * 2 + sub;
        const int e2 = pB * 2 + sub;
        const bool hasB = (pB < npairs) && (e2 < E);

        int r1, c1, r2 = 0, c2 = 0;
        if (is64) {
            // little-endian: low 32-bit word of int64 at index 2e
            r1 = ei32[2 * e1];        c1 = ei32[2 * (E + e1)];
            if (hasB) { r2 = ei32[2 * e2];  c2 = ei32[2 * (E + e2)]; }
        } else {
            r1 = ei32[e1];  c1 = ei32[E + e1];
            if (hasB) { r2 = ei32[e2];  c2 = ei32[E + e2]; }
        }

        uint4 a1 = *(const uint4*)(g_A16 + (size_t)r1 * 128 + sl * 8);
        uint4 b1 = *(const uint4*)(g_B16 + (size_t)c1 * 128 + sl * 8);
        uint4 a2 = make_uint4(0, 0, 0, 0), b2q = a2;
        if (hasB) {
            a2 = *(const uint4*)(g_A16 + (size_t)r2 * 128 + sl * 8);
            b2q = *(const uint4*)(g_B16 + (size_t)c2 * 128 + sl * 8);
        }

        float s1 = edge_dot(a1, b1, w2a, w2b);
        float s2 = edge_dot(a2, b2q, w2a, w2b);
#pragma unroll
        for (int o = 8; o; o >>= 1) {
            s1 += __shfl_xor_sync(0xffffffffu, s1, o);
            s2 += __shfl_xor_sync(0xffffffffu, s2, o);
        }

        if (sl == 0) {
            if (e1 < E) out[e1] = s1 + b2v;
            if (hasB)   out[e2] = s2 + b2v;
        }
    }
}

// ---------------------------------------------------------------------------
// Launch
// ---------------------------------------------------------------------------
extern "C" void kernel_launch(void* const* d_in, const int* in_sizes, int n_in,
                              void* d_out, int out_size)
{
    const float* z  = (const float*)d_in[0];
    const void*  ei = d_in[1];
    const float* W1 = (const float*)d_in[2];
    const float* b1 = (const float*)d_in[3];
    const float* W2 = (const float*)d_in[4];
    const float* b2 = (const float*)d_in[5];
    float* out = (float*)d_out;

    const int N = in_sizes[0] / D;   // 100000
    const int E = out_size;          // 800000

    cudaFuncSetAttribute(node_mma_kernel,
                         cudaFuncAttributeMaxDynamicSharedMemorySize, 52224);
    node_mma_kernel<<<296, 256, 52224>>>(z, W1, b1, N);

    edge_kernel<<<1184, 256>>>(ei, W2, b2, out, E, N);
}

// round 14
// speedup vs baseline: 5.6409x; 1.0247x over previous
#include <cuda_runtime.h>
#include <cuda_fp16.h>
#include <stdint.h>

#define D 128
#define NMAX 100000
#define WPITCH 136                   // fp16 elems per smem row (128 + 8 pad)
#define PITCHB 272                   // bytes

// ---------------------------------------------------------------------------
// Device scratch (static — no cudaMalloc allowed)
// ---------------------------------------------------------------------------
__device__ __align__(16) __half g_A16[(size_t)(NMAX + 128) * 128];  // z@W1[:128]
__device__ __align__(16) __half g_B16[(size_t)(NMAX + 128) * 128];  // z@W1[128:]+b1

// ---------------------------------------------------------------------------
// PTX helpers (sm_80-era only; safe on .target sm_103)
// ---------------------------------------------------------------------------
__device__ __forceinline__ uint32_t smem_u32(const void* p) {
    uint32_t a;
    asm("{ .reg .u64 t; cvta.to.shared.u64 t, %1; cvt.u32.u64 %0, t; }"
        : "=r"(a) : "l"(p));
    return a;
}

#define LDSM_X4(r0, r1, r2, r3, addr)                                           \
    asm volatile("ldmatrix.sync.aligned.m8n8.x4.shared.b16 {%0,%1,%2,%3},[%4];" \
                 : "=r"(r0), "=r"(r1), "=r"(r2), "=r"(r3) : "r"(addr))

#define LDSM_X2(r0, r1, addr)                                                \
    asm volatile("ldmatrix.sync.aligned.m8n8.x2.shared.b16 {%0,%1},[%2];"    \
                 : "=r"(r0), "=r"(r1) : "r"(addr))

#define MMA_F16(d, a0, a1, a2, a3, b0, b1)                                   \
    asm volatile("mma.sync.aligned.m16n8k16.row.col.f32.f16.f16.f32 "        \
                 "{%0,%1,%2,%3},{%4,%5,%6,%7},{%8,%9},{%0,%1,%2,%3};"        \
                 : "+f"((d)[0]), "+f"((d)[1]), "+f"((d)[2]), "+f"((d)[3])    \
                 : "r"(a0), "r"(a1), "r"(a2), "r"(a3), "r"(b0), "r"(b1))

// ---------------------------------------------------------------------------
// Node projection via mma.sync fp16 (fp32 accum), single pass:
//   A = z16 @ W16[:128],  B = z16 @ W16[128:] + b1
// 296 CTAs x 256 thr, 2 CTAs/SM. hb = bid&1 selects table; 64-row tiles,
// stride 148. Register-staged LDG pipeline (R9 loop order; convert of next
// tile moved BEFORE the global STG burst to overlap STS with STG drain).
// SMEM: conv0 17408 | conv1 17408 | epi 17408 = 52224 B
// ---------------------------------------------------------------------------
__global__ void __launch_bounds__(256, 2)
node_mma_kernel(const float* __restrict__ z, const float* __restrict__ W1,
                const float* __restrict__ b1, int N)
{
    extern __shared__ char smem[];
    const uint32_t OF_C0  = 0;
    const uint32_t OF_C1  = 17408;
    const uint32_t OF_EPI = 34816;

    const uint32_t sb = smem_u32(smem);
    const int tid = threadIdx.x;
    const int w = tid >> 5;
    const int lane = tid & 31;
    const int hb = blockIdx.x & 1;
    const int tstart = blockIdx.x >> 1;
    const int ntiles = (N + 63) / 64;

    float4 rawreg[8];
    auto issue_ldg = [&](int t) {
        const int rows_valid = N - t * 64;
        const float4* src = (const float4*)(z + (size_t)t * 64 * 128);
#pragma unroll
        for (int q = 0; q < 8; q++) {
            int idx = tid + q * 256;
            int m = idx >> 5, j = idx & 31;
            rawreg[q] = (m < rows_valid) ? src[m * 32 + j]
                                         : make_float4(0.f, 0.f, 0.f, 0.f);
        }
    };
    auto cvt_sts = [&](uint32_t convoff) {
#pragma unroll
        for (int q = 0; q < 8; q++) {
            int idx = tid + q * 256;
            int m = idx >> 5, j = idx & 31;
            half2 h0 = __floats2half2_rn(rawreg[q].x, rawreg[q].y);
            half2 h1 = __floats2half2_rn(rawreg[q].z, rawreg[q].w);
            *(uint2*)(smem + convoff + (uint32_t)(m * 272 + j * 8)) =
                make_uint2(*(uint32_t*)&h0, *(uint32_t*)&h1);
        }
    };

    if (tstart < ntiles) issue_ldg(tstart);

    // ---- W1 -> fp16 fragments in registers (16 cols per warp) ----
    uint32_t whf[16][2];
    {
        const int n0 = w * 16;
        const uint32_t stg = (uint32_t)(OF_C0 + w * 2176);   // 8 rows x 272B
        const uint32_t boffp = sb + stg
            + (uint32_t)((lane & 7) * 272 + ((lane >> 3) & 1) * 16);
#pragma unroll
        for (int half8 = 0; half8 < 2; half8++) {
#pragma unroll
            for (int q = 0; q < 32; q++) {
                int idx = lane + q * 32;
                int r = idx & 7, k = idx >> 3;
                float x = W1[(size_t)(hb * 128 + k) * 128 + n0 + half8 * 8 + r];
                *(__half*)(smem + stg + r * 272 + k * 2) = __float2half_rn(x);
            }
            __syncwarp();
#pragma unroll
            for (int ks = 0; ks < 8; ks++)
                LDSM_X2(whf[ks * 2 + half8][0], whf[ks * 2 + half8][1],
                        boffp + (uint32_t)(ks * 32));
            __syncwarp();
        }
    }
    __syncthreads();

    if (tstart < ntiles) cvt_sts(OF_C0);

    float2 bb0 = make_float2(0.f, 0.f), bb1 = bb0;
    if (hb) {
        int c = w * 16 + (lane & 3) * 2;
        bb0 = *(const float2*)(b1 + c);
        bb1 = *(const float2*)(b1 + c + 8);
    }
    __half* dsttab = hb ? g_B16 : g_A16;
    const uint32_t a_off = (uint32_t)((lane & 15) * WPITCH + (lane >> 4) * 8) * 2;
    const uint32_t Ah = sb + OF_C0 + a_off;

    int it = 0;
    for (int t = tstart; t < ntiles; t += 148) {
        const int tn = t + 148;
        __syncthreads();   // conv[it] visible; prev iter's epi reads done
        if (tn < ntiles) issue_ldg(tn);

        float acc[4][2][4];
#pragma unroll
        for (int mt = 0; mt < 4; mt++)
#pragma unroll
            for (int nt = 0; nt < 2; nt++)
#pragma unroll
                for (int q = 0; q < 4; q++) acc[mt][nt][q] = 0.f;

        // ---- MMA: 8 k-steps x 4 m-tiles x 2 MMAs (R9 loop order) ----
        const uint32_t Abase = Ah + (uint32_t)(it * 17408);
#pragma unroll
        for (int ks = 0; ks < 8; ks++) {
            const uint32_t ko = (uint32_t)ks * 32;
#pragma unroll
            for (int mt = 0; mt < 4; mt++) {
                uint32_t a0, a1, a2, a3;
                LDSM_X4(a0, a1, a2, a3, Abase + (uint32_t)(mt * 16 * 272) + ko);
                MMA_F16(acc[mt][0], a0, a1, a2, a3, whf[ks*2+0][0], whf[ks*2+0][1]);
                MMA_F16(acc[mt][1], a0, a1, a2, a3, whf[ks*2+1][0], whf[ks*2+1][1]);
            }
        }

        // ---- Epilogue: acc -> epi smem (conflict-free, pitch 272) ----
#pragma unroll
        for (int mt = 0; mt < 4; mt++) {
            int r = mt * 16 + (lane >> 2);
#pragma unroll
            for (int nt = 0; nt < 2; nt++) {
                float2 b = nt ? bb1 : bb0;
                uint32_t cbyte = (uint32_t)((w * 16 + nt * 8 + (lane & 3) * 2) * 2);
                half2 v0 = __floats2half2_rn(acc[mt][nt][0] + b.x, acc[mt][nt][1] + b.y);
                half2 v1 = __floats2half2_rn(acc[mt][nt][2] + b.x, acc[mt][nt][3] + b.y);
                *(half2*)(smem + OF_EPI + (uint32_t)r * 272 + cbyte) = v0;
                *(half2*)(smem + OF_EPI + (uint32_t)(r + 8) * 272 + cbyte) = v1;
            }
        }

        // ---- convert next tile NOW (STS overlaps the STG drain below) ----
        if (tn < ntiles) cvt_sts(it ? OF_C0 : OF_C1);
        __syncthreads();   // epi writes (and conv STS) visible

        // ---- Coalesced STG.128: 64 rows x 256 B ----
        {
            const int m0 = t * 64;
            const int rows_valid = N - m0;
#pragma unroll
            for (int p = 0; p < 4; p++) {
                int linear = p * 4096 + tid * 16;
                int row = linear >> 8;
                int cb = linear & 255;
                if (row < rows_valid)
                    *(uint4*)(dsttab + (size_t)(m0 + row) * 128 + (cb >> 1)) =
                        *(const uint4*)(smem + OF_EPI + row * 272 + cb);
            }
        }
        it ^= 1;
    }
}

// ---------------------------------------------------------------------------
// Edge pass: out[e] = relu(A16[row] + B16[col]) . W2 + b2
// HADD2+HMAX2 add/relu, fp32 dot. 16 lanes/edge, 2-pair unroll.
// At the LTS service floor (~10.5 TB/s) — exact R9 version.
// ---------------------------------------------------------------------------
__device__ __forceinline__ float edge_dot(uint4 a4, uint4 b4,
                                          float4 w2a, float4 w2b) {
    const half2 z2 = __floats2half2_rn(0.f, 0.f);
    half2 h0 = __hmax2(__hadd2(*(half2*)&a4.x, *(half2*)&b4.x), z2);
    half2 h1 = __hmax2(__hadd2(*(half2*)&a4.y, *(half2*)&b4.y), z2);
    half2 h2 = __hmax2(__hadd2(*(half2*)&a4.z, *(half2*)&b4.z), z2);
    half2 h3 = __hmax2(__hadd2(*(half2*)&a4.w, *(half2*)&b4.w), z2);
    float2 f0 = __half22float2(h0);
    float2 f1 = __half22float2(h1);
    float2 f2 = __half22float2(h2);
    float2 f3 = __half22float2(h3);
    return f0.x * w2a.x + f0.y * w2a.y + f1.x * w2a.z + f1.y * w2a.w
         + f2.x * w2b.x + f2.y * w2b.y + f3.x * w2b.z + f3.y * w2b.w;
}

__global__ void __launch_bounds__(256)
edge_kernel(const void* __restrict__ ei_raw,
            const float* __restrict__ W2,
            const float* __restrict__ b2,
            float* __restrict__ out, int E, int N)
{
    const long long* ei64 = (const long long*)ei_raw;
    const int*       ei32 = (const int*)ei_raw;

    int is64 = 1;
#pragma unroll
    for (int i = 0; i < 8; i++) {
        long long v = __ldg(&ei64[i]);
        if (v < 0 || v >= (long long)N) is64 = 0;
    }

    const int lane = threadIdx.x & 31;
    const int sub = lane >> 4;     // which edge of the pair
    const int sl  = lane & 15;     // lane within edge (8 dims)

    const float4 w2a = ((const float4*)W2)[sl * 2];
    const float4 w2b = ((const float4*)W2)[sl * 2 + 1];
    const float b2v = __ldg(b2);

    const int warp = (blockIdx.x * 256 + threadIdx.x) >> 5;
    const int nwarp = (gridDim.x * 256) >> 5;
    const int npairs = (E + 1) >> 1;

    for (int p = warp; p < npairs; p += 2 * nwarp) {
        const int pB = p + nwarp;
        const int e1 = p * 2 + sub;
        const int e2 = pB * 2 + sub;
        const bool hasB = (pB < npairs) && (e2 < E);

        int r1, c1, r2 = 0, c2 = 0;
        if (is64) {
            r1 = (int)ei64[e1];  c1 = (int)ei64[E + e1];
            if (hasB) { r2 = (int)ei64[e2];  c2 = (int)ei64[E + e2]; }
        } else {
            r1 = ei32[e1];  c1 = ei32[E + e1];
            if (hasB) { r2 = ei32[e2];  c2 = ei32[E + e2]; }
        }

        uint4 a1 = *(const uint4*)(g_A16 + (size_t)r1 * 128 + sl * 8);
        uint4 b1 = *(const uint4*)(g_B16 + (size_t)c1 * 128 + sl * 8);
        uint4 a2 = make_uint4(0, 0, 0, 0), b2q = a2;
        if (hasB) {
            a2 = *(const uint4*)(g_A16 + (size_t)r2 * 128 + sl * 8);
            b2q = *(const uint4*)(g_B16 + (size_t)c2 * 128 + sl * 8);
        }

        float s1 = edge_dot(a1, b1, w2a, w2b);
        float s2 = edge_dot(a2, b2q, w2a, w2b);
#pragma unroll
        for (int o = 8; o; o >>= 1) {
            s1 += __shfl_xor_sync(0xffffffffu, s1, o);
            s2 += __shfl_xor_sync(0xffffffffu, s2, o);
        }

        if (sl == 0) {
            if (e1 < E) out[e1] = s1 + b2v;
            if (hasB)   out[e2] = s2 + b2v;
        }
    }
}

// ---------------------------------------------------------------------------
// Launch
// ---------------------------------------------------------------------------
extern "C" void kernel_launch(void* const* d_in, const int* in_sizes, int n_in,
                              void* d_out, int out_size)
{
    const float* z  = (const float*)d_in[0];
    const void*  ei = d_in[1];
    const float* W1 = (const float*)d_in[2];
    const float* b1 = (const float*)d_in[3];
    const float* W2 = (const float*)d_in[4];
    const float* b2 = (const float*)d_in[5];
    float* out = (float*)d_out;

    const int N = in_sizes[0] / D;   // 100000
    const int E = out_size;          // 800000

    cudaFuncSetAttribute(node_mma_kernel,
                         cudaFuncAttributeMaxDynamicSharedMemorySize, 52224);
    node_mma_kernel<<<296, 256, 52224>>>(z, W1, b1, N);

    edge_kernel<<<1184, 256>>>(ei, W2, b2, out, E, N);
}